// round 1
// baseline (speedup 1.0000x reference)
#include <cuda_runtime.h>

#define L1D 16
#define IN_DIM 128
#define MAXN 65536

// Scratch: node-level hidden activations (allowed: __device__ globals)
__device__ float g_h1[MAXN * L1D];
__device__ float g_h2[MAXN * L1D];
__device__ int g_is64;

// ---------------------------------------------------------------------------
// Detect whether edge_index is int64 or int32.
// If int64 (little-endian, values in [0, 50000)), every odd 32-bit word of the
// first half of the buffer is 0. We only touch the first in_sizes[5] 32-bit
// words, which is safe under either interpretation.
// ---------------------------------------------------------------------------
__global__ void detect_kernel(const unsigned int* __restrict__ w, int n_words) {
    int stride = n_words / 2048;
    if (stride < 1) stride = 1;
    int wi = 2 * (threadIdx.x * stride) + 1;
    int nz = 0;
    if (wi < n_words) nz = (w[wi] != 0u) ? 1 : 0;
    int any = __syncthreads_or(nz);
    if (threadIdx.x == 0) g_is64 = any ? 0 : 1;
}

// ---------------------------------------------------------------------------
// Kernel 1: per-node tiny MLP.  h1 = relu(z @ w1_l1), h2 = relu(z @ w2_l1)
// Block = 256 threads handles 16 nodes; each thread computes one (node, col).
// ---------------------------------------------------------------------------
__global__ __launch_bounds__(256) void node_mlp_kernel(
    const float* __restrict__ z,
    const float* __restrict__ w1,
    const float* __restrict__ w2,
    int n_nodes)
{
    __shared__ float zs[16 * IN_DIM];     // 8 KB
    __shared__ float w1s[IN_DIM * L1D];   // 8 KB
    __shared__ float w2s[IN_DIM * L1D];   // 8 KB

    int tid = threadIdx.x;
    for (int i = tid; i < IN_DIM * L1D; i += 256) {
        w1s[i] = w1[i];
        w2s[i] = w2[i];
    }
    int nbase = blockIdx.x * 16;
    int nvalid = n_nodes - nbase;
    if (nvalid > 16) nvalid = 16;
    for (int i = tid; i < nvalid * IN_DIM; i += 256) {
        zs[i] = z[(size_t)nbase * IN_DIM + i];
    }
    __syncthreads();

    int nl  = tid >> 4;   // 0..15  local node
    int col = tid & 15;   // 0..15  output column
    int node = nbase + nl;
    if (node < n_nodes && node < MAXN) {
        float a1 = 0.f, a2 = 0.f;
        #pragma unroll 16
        for (int k = 0; k < IN_DIM; k++) {
            float zv = zs[nl * IN_DIM + k];
            a1 = fmaf(zv, w1s[k * L1D + col], a1);
            a2 = fmaf(zv, w2s[k * L1D + col], a2);
        }
        g_h1[node * L1D + col] = fmaxf(a1, 0.f);
        g_h2[node * L1D + col] = fmaxf(a2, 0.f);
    }
}

// ---------------------------------------------------------------------------
// Kernel 2: per-edge scoring. Persistent grid-stride blocks; edge-type weight
// tables staged once per block into shared memory.
//   out[e] = sigmoid( dot(h1[src], w1_l2[et]) + dot(h2[dst], w2_l2[et]) )
// ---------------------------------------------------------------------------
__global__ __launch_bounds__(256) void edge_kernel(
    const float* __restrict__ w1_l2,
    const float* __restrict__ w2_l2,
    const void* __restrict__ ei,
    const void* __restrict__ et,
    float* __restrict__ out,
    int n_edges, int n_etype)
{
    extern __shared__ float ws[];
    float* w1s = ws;
    float* w2s = ws + n_etype * L1D;
    for (int i = threadIdx.x; i < n_etype * L1D; i += blockDim.x) {
        w1s[i] = w1_l2[i];
        w2s[i] = w2_l2[i];
    }
    __syncthreads();

    const int is64 = g_is64;
    const int stride = gridDim.x * blockDim.x;

    for (int e = blockIdx.x * blockDim.x + threadIdx.x; e < n_edges; e += stride) {
        long long s, d, t;
        if (is64) {
            const long long* p = (const long long*)ei;
            s = p[e];
            d = p[(size_t)n_edges + e];
            t = ((const long long*)et)[e];
        } else {
            const int* p = (const int*)ei;
            s = p[e];
            d = p[(size_t)n_edges + e];
            t = ((const int*)et)[e];
        }

        const float4* ha = (const float4*)(g_h1 + s * L1D);
        const float4* hb = (const float4*)(g_h2 + d * L1D);
        float4 a0 = ha[0], a1 = ha[1], a2 = ha[2], a3 = ha[3];
        float4 b0 = hb[0], b1 = hb[1], b2 = hb[2], b3 = hb[3];

        const float4* ua = (const float4*)(w1s + t * L1D);
        const float4* ub = (const float4*)(w2s + t * L1D);
        float4 u0 = ua[0], u1 = ua[1], u2 = ua[2], u3 = ua[3];
        float4 v0 = ub[0], v1 = ub[1], v2 = ub[2], v3 = ub[3];

        float acc = 0.f;
        acc = fmaf(a0.x, u0.x, acc); acc = fmaf(a0.y, u0.y, acc);
        acc = fmaf(a0.z, u0.z, acc); acc = fmaf(a0.w, u0.w, acc);
        acc = fmaf(a1.x, u1.x, acc); acc = fmaf(a1.y, u1.y, acc);
        acc = fmaf(a1.z, u1.z, acc); acc = fmaf(a1.w, u1.w, acc);
        acc = fmaf(a2.x, u2.x, acc); acc = fmaf(a2.y, u2.y, acc);
        acc = fmaf(a2.z, u2.z, acc); acc = fmaf(a2.w, u2.w, acc);
        acc = fmaf(a3.x, u3.x, acc); acc = fmaf(a3.y, u3.y, acc);
        acc = fmaf(a3.z, u3.z, acc); acc = fmaf(a3.w, u3.w, acc);

        acc = fmaf(b0.x, v0.x, acc); acc = fmaf(b0.y, v0.y, acc);
        acc = fmaf(b0.z, v0.z, acc); acc = fmaf(b0.w, v0.w, acc);
        acc = fmaf(b1.x, v1.x, acc); acc = fmaf(b1.y, v1.y, acc);
        acc = fmaf(b1.z, v1.z, acc); acc = fmaf(b1.w, v1.w, acc);
        acc = fmaf(b2.x, v2.x, acc); acc = fmaf(b2.y, v2.y, acc);
        acc = fmaf(b2.z, v2.z, acc); acc = fmaf(b2.w, v2.w, acc);
        acc = fmaf(b3.x, v3.x, acc); acc = fmaf(b3.y, v3.y, acc);
        acc = fmaf(b3.z, v3.z, acc); acc = fmaf(b3.w, v3.w, acc);

        out[e] = 1.f / (1.f + __expf(-acc));
    }
}

// ---------------------------------------------------------------------------
// Launch. Inputs (metadata order): z, w1_l1, w1_l2, w2_l1, w2_l2,
// edge_index [2,E], edge_type [E].  Output: float32 [E].
// ---------------------------------------------------------------------------
extern "C" void kernel_launch(void* const* d_in, const int* in_sizes, int n_in,
                              void* d_out, int out_size) {
    const float* z     = (const float*)d_in[0];
    const float* w1_l1 = (const float*)d_in[1];
    const float* w1_l2 = (const float*)d_in[2];
    const float* w2_l1 = (const float*)d_in[3];
    const float* w2_l2 = (const float*)d_in[4];
    const void*  ei    = d_in[5];
    const void*  et    = d_in[6];
    float* out = (float*)d_out;

    int n_nodes = in_sizes[0] / IN_DIM;
    int n_etype = in_sizes[2] / L1D;
    int n_edges = out_size;

    detect_kernel<<<1, 1024>>>((const unsigned int*)ei, in_sizes[5]);

    int nblocks = (n_nodes + 15) / 16;
    node_mlp_kernel<<<nblocks, 256>>>(z, w1_l1, w2_l1, n_nodes);

    size_t smem = (size_t)2 * n_etype * L1D * sizeof(float);
    edge_kernel<<<1184, 256, smem>>>(w1_l2, w2_l2, ei, et, out, n_edges, n_etype);
}

// round 3
// speedup vs baseline: 1.4637x; 1.4637x over previous
#include <cuda_runtime.h>

#define L1D 16
#define IN_DIM 128
#define MAXN 65536
#define WSTRIDE 20   // padded smem row stride (floats) for weight tables

// Scratch: node-level hidden activations (allowed: __device__ globals)
__device__ float g_h1[MAXN * L1D];
__device__ float g_h2[MAXN * L1D];
__device__ int g_is64;

// ---------------------------------------------------------------------------
// Detect int64 vs int32 edge_index: sample first 32 odd 32-bit words.
// int64 node ids < 50000 => high words all 0. int32 => odd words are random
// node ids, P(all 32 zero) ~ (1/50000)^32 ~ 0.
// ---------------------------------------------------------------------------
__global__ void detect_kernel(const unsigned int* __restrict__ w, int n_words) {
    int wi = 2 * threadIdx.x + 1;
    int nz = 0;
    if (wi < n_words) nz = (w[wi] != 0u) ? 1 : 0;
    unsigned any = __ballot_sync(0xFFFFFFFFu, nz);
    if (threadIdx.x == 0) g_is64 = (any == 0u) ? 1 : 0;
}

// ---------------------------------------------------------------------------
// Kernel 1: per-node tiny MLP.  h1 = relu(z @ w1_l1), h2 = relu(z @ w2_l1)
// Block = 256 threads handles 16 nodes; one thread per (node, col).
// ---------------------------------------------------------------------------
__global__ __launch_bounds__(256) void node_mlp_kernel(
    const float* __restrict__ z,
    const float* __restrict__ w1,
    const float* __restrict__ w2,
    int n_nodes)
{
    __shared__ float zs[16 * IN_DIM];     // 8 KB
    __shared__ float w1s[IN_DIM * L1D];   // 8 KB
    __shared__ float w2s[IN_DIM * L1D];   // 8 KB

    int tid = threadIdx.x;
    // stage weights (512 float4 each)
    {
        const float4* w1v = (const float4*)w1;
        const float4* w2v = (const float4*)w2;
        #pragma unroll
        for (int i = 0; i < 2; i++) {
            ((float4*)w1s)[tid + 256 * i] = w1v[tid + 256 * i];
            ((float4*)w2s)[tid + 256 * i] = w2v[tid + 256 * i];
        }
    }
    int nbase = blockIdx.x * 16;
    int nvalid = n_nodes - nbase;
    if (nvalid > 16) nvalid = 16;
    {
        const float4* z4 = (const float4*)(z + (size_t)nbase * IN_DIM);
        for (int i = tid; i < nvalid * (IN_DIM / 4); i += 256)
            ((float4*)zs)[i] = z4[i];
    }
    __syncthreads();

    int nl  = tid >> 4;   // local node 0..15
    int col = tid & 15;   // output col 0..15
    int node = nbase + nl;
    if (node < n_nodes) {
        float a1 = 0.f, a2 = 0.f;
        #pragma unroll 16
        for (int k = 0; k < IN_DIM; k++) {
            float zv = zs[nl * IN_DIM + k];
            a1 = fmaf(zv, w1s[k * L1D + col], a1);
            a2 = fmaf(zv, w2s[k * L1D + col], a2);
        }
        g_h1[node * L1D + col] = fmaxf(a1, 0.f);
        g_h2[node * L1D + col] = fmaxf(a2, 0.f);
    }
}

// ---------------------------------------------------------------------------
// Kernel 2: per-edge scoring, 4 lanes per edge.
// Each 4-lane group handles one edge; each lane loads one float4 quarter of
// h1[src], h2[dst] and the smem weight rows, does 8 FMAs, then a 2-step
// shfl_xor reduction. Cuts divergent-gather L1 wavefronts 4x vs 1 thread/edge.
// Weight rows padded to stride 20 so random-type LDS rotates bank groups.
// ---------------------------------------------------------------------------
__global__ __launch_bounds__(256) void edge_kernel(
    const float* __restrict__ w1_l2,
    const float* __restrict__ w2_l2,
    const void* __restrict__ ei,
    const void* __restrict__ et,
    float* __restrict__ out,
    int n_edges, int n_etype)
{
    extern __shared__ float ws[];
    float* w1s = ws;
    float* w2s = ws + n_etype * WSTRIDE;
    // stage weights: one float4 (quarter row) per thread-iteration
    for (int i = threadIdx.x; i < n_etype * 4; i += blockDim.x) {
        int r = i >> 2, q = i & 3;
        *(float4*)(w1s + r * WSTRIDE + q * 4) = ((const float4*)w1_l2)[i];
        *(float4*)(w2s + r * WSTRIDE + q * 4) = ((const float4*)w2_l2)[i];
    }
    __syncthreads();

    const int is64 = g_is64;
    const int sub = threadIdx.x & 3;                    // quarter 0..3
    const int lane_group = (threadIdx.x >> 2) & 7;      // group within warp 0..7
    const int group0 = (blockIdx.x * blockDim.x + threadIdx.x) >> 2;
    const int gstride = (gridDim.x * blockDim.x) >> 2;
    const int warp_base0 = group0 - lane_group;         // warp-uniform

    const long long* p64 = (const long long*)ei;
    const int*       p32 = (const int*)ei;
    const long long* t64 = (const long long*)et;
    const int*       t32 = (const int*)et;

    for (int base = warp_base0; base < n_edges; base += gstride) {
        int e  = base + lane_group;
        int ec = e < n_edges ? e : n_edges - 1;

        int s, d, t;
        if (is64) {
            s = (int)__ldg(p64 + ec);
            d = (int)__ldg(p64 + (size_t)n_edges + ec);
            t = (int)__ldg(t64 + ec);
        } else {
            s = __ldg(p32 + ec);
            d = __ldg(p32 + (size_t)n_edges + ec);
            t = __ldg(t32 + ec);
        }

        float4 a = *(const float4*)(g_h1 + s * L1D + sub * 4);
        float4 b = *(const float4*)(g_h2 + d * L1D + sub * 4);
        float4 u = *(const float4*)(w1s + t * WSTRIDE + sub * 4);
        float4 v = *(const float4*)(w2s + t * WSTRIDE + sub * 4);

        float acc;
        acc = a.x * u.x;
        acc = fmaf(a.y, u.y, acc);
        acc = fmaf(a.z, u.z, acc);
        acc = fmaf(a.w, u.w, acc);
        acc = fmaf(b.x, v.x, acc);
        acc = fmaf(b.y, v.y, acc);
        acc = fmaf(b.z, v.z, acc);
        acc = fmaf(b.w, v.w, acc);

        acc += __shfl_xor_sync(0xFFFFFFFFu, acc, 1);
        acc += __shfl_xor_sync(0xFFFFFFFFu, acc, 2);

        if (sub == 0 && e < n_edges)
            out[e] = 1.f / (1.f + __expf(-acc));
    }
}

// ---------------------------------------------------------------------------
// Launch. Inputs (metadata order): z, w1_l1, w1_l2, w2_l1, w2_l2,
// edge_index [2,E], edge_type [E].  Output: float32 [E].
// ---------------------------------------------------------------------------
extern "C" void kernel_launch(void* const* d_in, const int* in_sizes, int n_in,
                              void* d_out, int out_size) {
    const float* z     = (const float*)d_in[0];
    const float* w1_l1 = (const float*)d_in[1];
    const float* w1_l2 = (const float*)d_in[2];
    const float* w2_l1 = (const float*)d_in[3];
    const float* w2_l2 = (const float*)d_in[4];
    const void*  ei    = d_in[5];
    const void*  et    = d_in[6];
    float* out = (float*)d_out;

    int n_nodes = in_sizes[0] / IN_DIM;
    int n_etype = in_sizes[2] / L1D;
    int n_edges = out_size;

    detect_kernel<<<1, 32>>>((const unsigned int*)ei, in_sizes[5]);

    int nblocks = (n_nodes + 15) / 16;
    node_mlp_kernel<<<nblocks, 256>>>(z, w1_l1, w2_l1, n_nodes);

    size_t smem = (size_t)2 * n_etype * WSTRIDE * sizeof(float);
    edge_kernel<<<1184, 256, smem>>>(w1_l2, w2_l2, ei, et, out, n_edges, n_etype);
}

// round 4
// speedup vs baseline: 1.8294x; 1.2499x over previous
#include <cuda_runtime.h>

#define L1D 16
#define IN_DIM 128
#define MAXN 65536
#define WSTRIDE 20    // padded smem row stride (floats) for edge weight tables
#define ZSTRIDE 132   // padded smem row stride for z tile / transposed weights
#define NPB 32        // nodes per block in node_mlp

// Scratch: node-level hidden activations (allowed: __device__ globals)
__device__ float g_h1[MAXN * L1D];
__device__ float g_h2[MAXN * L1D];

// packed f32x2 fma: d = a*b + d (elementwise on two packed floats)
__device__ __forceinline__ void fma_f32x2(unsigned long long& d,
                                          unsigned long long a,
                                          unsigned long long b) {
    asm("fma.rn.f32x2 %0, %1, %2, %0;" : "+l"(d) : "l"(a), "l"(b));
}

__device__ __forceinline__ float unpack_sum(unsigned long long v) {
    float lo = __uint_as_float((unsigned)(v & 0xFFFFFFFFu));
    float hi = __uint_as_float((unsigned)(v >> 32));
    return lo + hi;
}

// ---------------------------------------------------------------------------
// Kernel 1: per-node tiny MLP.  h1 = relu(z @ w1_l1), h2 = relu(z @ w2_l1)
// Block = 128 threads, 32 nodes/block. Warp = 16 cols x 2 slots; each thread
// computes 4 nodes for its column. Weights transposed (col-major, padded
// stride) in smem -> float4 loads; z tile padded. Inner math uses packed
// fma.rn.f32x2 (2 FMA/instr) to halve FMA issue.
// ---------------------------------------------------------------------------
__global__ __launch_bounds__(128) void node_mlp_kernel(
    const float* __restrict__ z,
    const float* __restrict__ w1,
    const float* __restrict__ w2,
    int n_nodes)
{
    __shared__ float zs[NPB * ZSTRIDE];        // 16896 B
    __shared__ float w1T[L1D * ZSTRIDE];       // 8448 B (col-major: [col][k])
    __shared__ float w2T[L1D * ZSTRIDE];       // 8448 B

    const int tid = threadIdx.x;
    const int nbase = blockIdx.x * NPB;

    // stage transposed weights: w{1,2} are [k][col] row-major (128x16)
    for (int i = tid; i < IN_DIM * L1D; i += 128) {
        int k = i >> 4, col = i & 15;
        w1T[col * ZSTRIDE + k] = w1[i];
        w2T[col * ZSTRIDE + k] = w2[i];
    }
    // stage z tile (coalesced float4 reads, padded rows)
    {
        const float4* z4 = (const float4*)(z + (size_t)nbase * IN_DIM);
        for (int i = tid; i < NPB * (IN_DIM / 4); i += 128) {
            int row = i >> 5, q = i & 31;
            if (nbase + row < n_nodes)
                *(float4*)(zs + row * ZSTRIDE + q * 4) = z4[i];
        }
    }
    __syncthreads();

    const int col  = tid & 15;
    const int slot = (tid >> 4) & 1;
    const int warp = tid >> 5;
    const int nloc0 = warp * 8 + slot * 4;   // 4 consecutive local nodes

    unsigned long long acc1[4][2] = {}, acc2[4][2] = {};

    #pragma unroll 8
    for (int k = 0; k < IN_DIM; k += 4) {
        ulonglong2 wa = *(const ulonglong2*)(w1T + col * ZSTRIDE + k);
        ulonglong2 wb = *(const ulonglong2*)(w2T + col * ZSTRIDE + k);
        #pragma unroll
        for (int j = 0; j < 4; j++) {
            ulonglong2 zv = *(const ulonglong2*)(zs + (nloc0 + j) * ZSTRIDE + k);
            fma_f32x2(acc1[j][0], zv.x, wa.x);
            fma_f32x2(acc1[j][1], zv.y, wa.y);
            fma_f32x2(acc2[j][0], zv.x, wb.x);
            fma_f32x2(acc2[j][1], zv.y, wb.y);
        }
    }

    #pragma unroll
    for (int j = 0; j < 4; j++) {
        int node = nbase + nloc0 + j;
        if (node < n_nodes) {
            float a1 = unpack_sum(acc1[j][0]) + unpack_sum(acc1[j][1]);
            float a2 = unpack_sum(acc2[j][0]) + unpack_sum(acc2[j][1]);
            g_h1[node * L1D + col] = fmaxf(a1, 0.f);
            g_h2[node * L1D + col] = fmaxf(a2, 0.f);
        }
    }
}

// ---------------------------------------------------------------------------
// Kernel 2: per-edge scoring, 4 lanes per edge. Inline int64/int32 detection
// in the block prologue (int64 ids < 50000 => odd 32-bit words are all 0).
// ---------------------------------------------------------------------------
__global__ __launch_bounds__(256) void edge_kernel(
    const float* __restrict__ w1_l2,
    const float* __restrict__ w2_l2,
    const void* __restrict__ ei,
    const void* __restrict__ et,
    float* __restrict__ out,
    int n_edges, int n_etype)
{
    extern __shared__ float ws[];
    float* w1s = ws;
    float* w2s = ws + n_etype * WSTRIDE;
    __shared__ int s_is64;

    if (threadIdx.x < 32) {
        unsigned v = ((const unsigned*)ei)[2 * threadIdx.x + 1];
        unsigned any = __ballot_sync(0xFFFFFFFFu, v != 0u);
        if (threadIdx.x == 0) s_is64 = (any == 0u) ? 1 : 0;
    }
    // stage weights: one float4 (quarter row) per thread-iteration
    for (int i = threadIdx.x; i < n_etype * 4; i += blockDim.x) {
        int r = i >> 2, q = i & 3;
        *(float4*)(w1s + r * WSTRIDE + q * 4) = ((const float4*)w1_l2)[i];
        *(float4*)(w2s + r * WSTRIDE + q * 4) = ((const float4*)w2_l2)[i];
    }
    __syncthreads();

    const int is64 = s_is64;
    const int sub = threadIdx.x & 3;                    // quarter 0..3
    const int lane_group = (threadIdx.x >> 2) & 7;      // group within warp 0..7
    const int group0 = (blockIdx.x * blockDim.x + threadIdx.x) >> 2;
    const int gstride = (gridDim.x * blockDim.x) >> 2;
    const int warp_base0 = group0 - lane_group;         // warp-uniform

    const long long* p64 = (const long long*)ei;
    const int*       p32 = (const int*)ei;
    const long long* t64 = (const long long*)et;
    const int*       t32 = (const int*)et;

    for (int base = warp_base0; base < n_edges; base += gstride) {
        int e  = base + lane_group;
        int ec = e < n_edges ? e : n_edges - 1;

        int s, d, t;
        if (is64) {
            s = (int)__ldg(p64 + ec);
            d = (int)__ldg(p64 + (size_t)n_edges + ec);
            t = (int)__ldg(t64 + ec);
        } else {
            s = __ldg(p32 + ec);
            d = __ldg(p32 + (size_t)n_edges + ec);
            t = __ldg(t32 + ec);
        }

        float4 a = *(const float4*)(g_h1 + s * L1D + sub * 4);
        float4 b = *(const float4*)(g_h2 + d * L1D + sub * 4);
        float4 u = *(const float4*)(w1s + t * WSTRIDE + sub * 4);
        float4 v = *(const float4*)(w2s + t * WSTRIDE + sub * 4);

        float acc;
        acc = a.x * u.x;
        acc = fmaf(a.y, u.y, acc);
        acc = fmaf(a.z, u.z, acc);
        acc = fmaf(a.w, u.w, acc);
        acc = fmaf(b.x, v.x, acc);
        acc = fmaf(b.y, v.y, acc);
        acc = fmaf(b.z, v.z, acc);
        acc = fmaf(b.w, v.w, acc);

        acc += __shfl_xor_sync(0xFFFFFFFFu, acc, 1);
        acc += __shfl_xor_sync(0xFFFFFFFFu, acc, 2);

        if (sub == 0 && e < n_edges)
            out[e] = 1.f / (1.f + __expf(-acc));
    }
}

// ---------------------------------------------------------------------------
// Launch. Inputs (metadata order): z, w1_l1, w1_l2, w2_l1, w2_l2,
// edge_index [2,E], edge_type [E].  Output: float32 [E].
// ---------------------------------------------------------------------------
extern "C" void kernel_launch(void* const* d_in, const int* in_sizes, int n_in,
                              void* d_out, int out_size) {
    const float* z     = (const float*)d_in[0];
    const float* w1_l1 = (const float*)d_in[1];
    const float* w1_l2 = (const float*)d_in[2];
    const float* w2_l1 = (const float*)d_in[3];
    const float* w2_l2 = (const float*)d_in[4];
    const void*  ei    = d_in[5];
    const void*  et    = d_in[6];
    float* out = (float*)d_out;

    int n_nodes = in_sizes[0] / IN_DIM;
    int n_etype = in_sizes[2] / L1D;
    int n_edges = out_size;

    int nblocks = (n_nodes + NPB - 1) / NPB;
    node_mlp_kernel<<<nblocks, 128>>>(z, w1_l1, w2_l1, n_nodes);

    size_t smem = (size_t)2 * n_etype * WSTRIDE * sizeof(float);
    edge_kernel<<<1036, 256, smem>>>(w1_l2, w2_l2, ei, et, out, n_edges, n_etype);
}